// round 3
// baseline (speedup 1.0000x reference)
#include <cuda_runtime.h>

#define Bq   256
#define Tq   1024
#define NUMq 126
#define LBLq 128
#define NSM  148   // classic placement LUT pairs bid with bid+148 on the same SM

__device__ int d_perm[Bq];

// Rank sequences by length (desc) so each SM's CTA pair sums to ~max_len steps.
__global__ void rank_kernel(const int* __restrict__ lens) {
    __shared__ int sl[Bq];
    int i = threadIdx.x;
    int li = lens[i];
    sl[i] = li;
    __syncthreads();
    int r = 0;
    #pragma unroll 8
    for (int k = 0; k < Bq; ++k) {
        int lk = sl[k];
        r += (lk > li) || (lk == li && k < i);
    }
    d_perm[r] = i;
}

__device__ __forceinline__ void fma2(unsigned long long& d,
                                     unsigned long long a, unsigned long long b) {
    asm("fma.rn.f32x2 %0, %1, %2, %0;" : "+l"(d) : "l"(a), "l"(b));
}
__device__ __forceinline__ unsigned long long add2(unsigned long long a,
                                                   unsigned long long b) {
    unsigned long long d;
    asm("add.rn.f32x2 %0, %1, %2;" : "=l"(d) : "l"(a), "l"(b));
    return d;
}
__device__ __forceinline__ unsigned long long pack2(float lo, float hi) {
    unsigned long long d;
    asm("mov.b64 %0, {%1, %2};" : "=l"(d) : "f"(lo), "f"(hi));
    return d;
}
__device__ __forceinline__ void unpack2(unsigned long long d, float& lo, float& hi) {
    asm("mov.b64 {%0, %1}, %2;" : "=f"(lo), "=f"(hi) : "l"(d));
}

__global__ __launch_bounds__(256, 2)
void crf_kernel(const float* __restrict__ logits,
                const int*   __restrict__ labels,
                const int*   __restrict__ lens,
                const float* __restrict__ trans,
                float*       __restrict__ out) {
    const int bid  = blockIdx.x;
    const int slot = (bid < NSM) ? bid : (Bq - 1 - (bid - NSM));
    const int b    = d_perm[slot];
    const int len  = lens[b];
    const int tid  = threadIdx.x;
    const int wid  = tid >> 5;
    const int lid  = tid & 31;
    const int rin  = lid & 15;      // row within warp
    const int h    = lid >> 4;      // k-half (0 or 1)
    const int row  = wid * 16 + rin;            // output label this thread serves
    const bool act = (row < NUMq);

    __shared__ __align__(16) float abuf[2][LBLq];  // linear alpha, double buffered
    __shared__ float part[8];                      // per-warp normalizer partials
    __shared__ float red[8];                       // reduction scratch

    // ---- expT half-row: R2[kk] covers k in [h*64, h*64+64) of row `row` ----
    unsigned long long R2[32];
    {
        const float4* tr = (const float4*)(trans + row * LBLq + h * 64);
        #pragma unroll
        for (int k4 = 0; k4 < 16; ++k4) {
            float4 v = tr[k4];
            R2[2 * k4 + 0] = pack2(__expf(v.x), __expf(v.y));
            R2[2 * k4 + 1] = pack2(__expf(v.z), __expf(v.w));
        }
    }

    // ---- gold path score (cooperative over t) ----
    const int lb = b * Tq;
    const float* lgb = logits + (size_t)lb * NUMq;
    float g = 0.f;
    for (int t = tid; t < len; t += 256) {
        int lab = labels[lb + t];
        g += lgb[t * NUMq + lab];                       // unary
        int prev = (t == 0) ? (LBLq - 2) : labels[lb + t - 1];
        g += trans[lab * LBLq + prev];                  // binary
    }
    if (tid == 0) g += trans[(LBLq - 1) * LBLq + labels[lb + len - 1]];
    g += __shfl_xor_sync(0xffffffffu, g, 16);
    g += __shfl_xor_sync(0xffffffffu, g, 8);
    g += __shfl_xor_sync(0xffffffffu, g, 4);
    g += __shfl_xor_sync(0xffffffffu, g, 2);
    g += __shfl_xor_sync(0xffffffffu, g, 1);
    if (lid == 0) red[wid] = g;
    __syncthreads();
    float gold = 0.f;
    if (tid == 0)
        gold = ((red[0] + red[1]) + (red[2] + red[3])) +
               ((red[4] + red[5]) + (red[6] + red[7]));

    // ---- init: alpha0 = onehot(start=126) in linear space ----
    if (tid < LBLq) abuf[0][tid] = (tid == (LBLq - 2)) ? 1.0f : 0.0f;
    if (tid < 8) part[tid] = (tid == 0) ? 1.0f : 0.0f;  // virtual c_{-1} = 1

    const float* lgcol = lgb + row;

    // logit queues: current group's 4 and next group's 4 (per-row stream)
    float curq[4], nxtq[4];
    #pragma unroll
    for (int q = 0; q < 4; ++q)
        curq[q] = (act && q < len) ? lgcol[q * NUMq] : 0.f;
    #pragma unroll
    for (int q = 0; q < 4; ++q)
        nxtq[q] = (act && (4 + q) < len) ? lgcol[(4 + q) * NUMq] : 0.f;

    float logc = 0.f;
    float inv  = 1.0f;
    __syncthreads();

    // ---- scaled forward scan, normalization amortized over groups of 4 ----
    for (int t = 0; t < len; ++t) {
        const int ph = t & 3;
        const int rb = t & 1, wb = rb ^ 1;

        if (ph == 0) {
            float total = ((part[0] + part[1]) + (part[2] + part[3])) +
                          ((part[4] + part[5]) + (part[6] + part[7]));
            inv   = __fdividef(1.0f, total);
            logc += __logf(total);
            if (t) {
                #pragma unroll
                for (int q = 0; q < 4; ++q) curq[q] = nxtq[q];
                #pragma unroll
                for (int q = 0; q < 4; ++q)
                    nxtq[q] = (act && (t + 4 + q) < len) ? lgcol[(t + 4 + q) * NUMq] : 0.f;
            }
        }

        float w = act ? __expf(curq[ph]) : 0.f;
        if (ph == 0) w *= inv;

        // half-dot: sum over k in [h*64, h*64+64) of expT[row,k] * alpha[k]
        const ulonglong2* aa = (const ulonglong2*)(abuf[rb] + h * 64);
        unsigned long long acc[4];
        acc[0] = acc[1] = acc[2] = acc[3] = 0ull;
        #pragma unroll
        for (int kk = 0; kk < 16; ++kk) {
            ulonglong2 a = aa[kk];
            fma2(acc[(2 * kk) & 3],     R2[2 * kk],     a.x);
            fma2(acc[(2 * kk + 1) & 3], R2[2 * kk + 1], a.y);
        }
        unsigned long long sT = add2(add2(acc[0], acc[1]), add2(acc[2], acc[3]));
        float lo, hi;
        unpack2(sT, lo, hi);
        float ps = lo + hi;
        ps += __shfl_xor_sync(0xffffffffu, ps, 16);   // combine the two k-halves
        float v = w * ps;                              // identical on lane pairs
        if (h == 0) abuf[wb][row] = v;

        // normalizer for the next group: butterfly over the 16 rows of this warp
        if (ph == 3 && (t + 1 < len)) {
            float s = v;
            s += __shfl_xor_sync(0xffffffffu, s, 8);
            s += __shfl_xor_sync(0xffffffffu, s, 4);
            s += __shfl_xor_sync(0xffffffffu, s, 2);
            s += __shfl_xor_sync(0xffffffffu, s, 1);
            if (lid == 0) part[wid] = s;
        }
        __syncthreads();
    }

    // ---- finish: alpha *= exp(trans[end]), norm = logc + log(sum) ----
    const int rbf = len & 1;
    float fv = 0.f;
    if (tid < LBLq)
        fv = abuf[rbf][tid] * __expf(trans[(LBLq - 1) * LBLq + tid]);
    fv += __shfl_xor_sync(0xffffffffu, fv, 16);
    fv += __shfl_xor_sync(0xffffffffu, fv, 8);
    fv += __shfl_xor_sync(0xffffffffu, fv, 4);
    fv += __shfl_xor_sync(0xffffffffu, fv, 2);
    fv += __shfl_xor_sync(0xffffffffu, fv, 1);
    if (lid == 0) red[wid] = fv;
    __syncthreads();
    if (tid == 0) {
        float fs = ((red[0] + red[1]) + (red[2] + red[3])) +
                   ((red[4] + red[5]) + (red[6] + red[7]));
        out[b] = gold - (logc + __logf(fs));
    }
}

extern "C" void kernel_launch(void* const* d_in, const int* in_sizes, int n_in,
                              void* d_out, int out_size) {
    const float* logits = (const float*)d_in[0];
    const int*   labels = (const int*)d_in[1];
    const int*   lens   = (const int*)d_in[2];
    const float* trans  = (const float*)d_in[3];
    float*       out    = (float*)d_out;

    rank_kernel<<<1, Bq>>>(lens);
    crf_kernel<<<Bq, 256>>>(logits, labels, lens, trans, out);
}

// round 4
// speedup vs baseline: 1.0086x; 1.0086x over previous
#include <cuda_runtime.h>

#define Bq   256
#define Tq   1024
#define NUMq 126
#define LBLq 128

__device__ int d_perm[Bq];

// Rank sequences by length (desc). Sub-group pairing (cta, 255-cta) then
// guarantees long+short share an SM regardless of the bid->SM placement LUT.
__global__ void rank_kernel(const int* __restrict__ lens) {
    __shared__ int sl[Bq];
    int i = threadIdx.x;
    int li = lens[i];
    sl[i] = li;
    __syncthreads();
    int r = 0;
    #pragma unroll 8
    for (int k = 0; k < Bq; ++k) {
        int lk = sl[k];
        r += (lk > li) || (lk == li && k < i);
    }
    d_perm[r] = i;
}

__device__ __forceinline__ void fma2(unsigned long long& d,
                                     unsigned long long a, unsigned long long b) {
    asm("fma.rn.f32x2 %0, %1, %2, %0;" : "+l"(d) : "l"(a), "l"(b));
}
__device__ __forceinline__ unsigned long long add2(unsigned long long a,
                                                   unsigned long long b) {
    unsigned long long d;
    asm("add.rn.f32x2 %0, %1, %2;" : "=l"(d) : "l"(a), "l"(b));
    return d;
}
__device__ __forceinline__ unsigned long long pack2(float lo, float hi) {
    unsigned long long d;
    asm("mov.b64 %0, {%1, %2};" : "=l"(d) : "f"(lo), "f"(hi));
    return d;
}
__device__ __forceinline__ void unpack2(unsigned long long d, float& lo, float& hi) {
    asm("mov.b64 {%0, %1}, %2;" : "=f"(lo), "=f"(hi) : "l"(d));
}

__global__ __launch_bounds__(256, 1)
void crf_kernel(const float* __restrict__ logits,
                const int*   __restrict__ labels,
                const int*   __restrict__ lens,
                const float* __restrict__ trans,
                float*       __restrict__ out) {
    const int cta  = blockIdx.x;           // 0..127
    const int sub  = threadIdx.x >> 7;     // which sub-group (0 or 1)
    const int j    = threadIdx.x & 127;    // row / label
    const int wid4 = (threadIdx.x >> 5) & 3;
    const int lid  = threadIdx.x & 31;
    const int barid = sub + 1;             // named barrier per sub-group

    const int slot = sub ? (Bq - 1 - cta) : cta;   // long + short on same SM
    const int b    = d_perm[slot];
    const int len  = lens[b];

    __shared__ __align__(16) float abuf[2][2][LBLq];  // [sub][buf][label]
    __shared__ float part[2][4];
    __shared__ float red[2][4];

    #define SUBBAR() asm volatile("bar.sync %0, 128;" :: "r"(barid) : "memory")

    // ---- expT row j, packed into 64 f32x2 registers ----
    unsigned long long R2[LBLq / 2];
    {
        const float4* trow = (const float4*)(trans + j * LBLq);
        #pragma unroll
        for (int k4 = 0; k4 < LBLq / 4; ++k4) {
            float4 v = trow[k4];
            R2[2 * k4 + 0] = pack2(__expf(v.x), __expf(v.y));
            R2[2 * k4 + 1] = pack2(__expf(v.z), __expf(v.w));
        }
    }

    // ---- gold path score (cooperative over t within sub-group) ----
    const int lb = b * Tq;
    const float* lgb = logits + (size_t)lb * NUMq;
    float g = 0.f;
    for (int t = j; t < len; t += 128) {
        int lab = labels[lb + t];
        g += lgb[t * NUMq + lab];                       // unary
        int prev = (t == 0) ? (LBLq - 2) : labels[lb + t - 1];
        g += trans[lab * LBLq + prev];                  // binary
    }
    if (j == 0) g += trans[(LBLq - 1) * LBLq + labels[lb + len - 1]];
    g += __shfl_xor_sync(0xffffffffu, g, 16);
    g += __shfl_xor_sync(0xffffffffu, g, 8);
    g += __shfl_xor_sync(0xffffffffu, g, 4);
    g += __shfl_xor_sync(0xffffffffu, g, 2);
    g += __shfl_xor_sync(0xffffffffu, g, 1);
    if (lid == 0) red[sub][wid4] = g;
    SUBBAR();
    float gold = 0.f;
    if (j == 0)
        gold = (red[sub][0] + red[sub][1]) + (red[sub][2] + red[sub][3]);

    // ---- init: alpha0 = onehot(start=126) in linear space ----
    abuf[sub][0][j] = (j == (LBLq - 2)) ? 1.0f : 0.0f;
    if (j < 4) part[sub][j] = (j == 0) ? 1.0f : 0.0f;   // virtual c_{-1} = 1

    const bool   act   = (j < NUMq);
    const float* lgcol = lgb + (act ? j : 0);

    // logit queues: current group's 4 and next group's 4 (clamped addresses)
    float curq[4], nxtq[4];
    #pragma unroll
    for (int q = 0; q < 4; ++q) {
        int tt = (q < len) ? q : (len - 1);
        curq[q] = act ? lgcol[tt * NUMq] : -1000.f;
    }
    #pragma unroll
    for (int q = 0; q < 4; ++q) {
        int tt = (4 + q < len) ? (4 + q) : (len - 1);
        nxtq[q] = act ? lgcol[tt * NUMq] : -1000.f;
    }

    float logc = 0.f;
    float inv  = 1.0f;
    SUBBAR();

    // ---- scaled forward scan, unrolled by 4, normalization amortized ----
    for (int t0 = 0; t0 < len; t0 += 4) {
        #pragma unroll
        for (int ph = 0; ph < 4; ++ph) {
            const int t = t0 + ph;
            if (t < len) {
                const int rb = ph & 1, wb = rb ^ 1;   // t0 multiple of 4

                if (ph == 0) {
                    float total = (part[sub][0] + part[sub][1]) +
                                  (part[sub][2] + part[sub][3]);
                    inv   = __fdividef(1.0f, total);
                    logc += __logf(total);
                    if (t0) {
                        #pragma unroll
                        for (int q = 0; q < 4; ++q) curq[q] = nxtq[q];
                        #pragma unroll
                        for (int q = 0; q < 4; ++q) {
                            int tt = (t0 + 4 + q < len) ? (t0 + 4 + q) : (len - 1);
                            nxtq[q] = act ? lgcol[tt * NUMq] : -1000.f;
                        }
                    }
                }

                float w = __expf(curq[ph]);           // 0 for inactive rows
                if (ph == 0) w *= inv;

                // dot: sum_k expT[j,k] * alpha[k] — packed f32x2, 8 accs
                const ulonglong2* aa = (const ulonglong2*)abuf[sub][rb];
                unsigned long long acc[8];
                #pragma unroll
                for (int k = 0; k < 8; ++k) acc[k] = 0ull;
                #pragma unroll
                for (int kk = 0; kk < 32; ++kk) {
                    ulonglong2 a = aa[kk];
                    fma2(acc[(2 * kk) & 7],     R2[2 * kk],     a.x);
                    fma2(acc[(2 * kk + 1) & 7], R2[2 * kk + 1], a.y);
                }
                unsigned long long sA = add2(add2(acc[0], acc[1]),
                                             add2(acc[2], acc[3]));
                unsigned long long sB = add2(add2(acc[4], acc[5]),
                                             add2(acc[6], acc[7]));
                unsigned long long sT = add2(sA, sB);
                float lo, hi;
                unpack2(sT, lo, hi);
                float v = w * (lo + hi);
                abuf[sub][wb][j] = v;

                // normalizer for the next group
                if (ph == 3) {
                    float s = v;
                    s += __shfl_xor_sync(0xffffffffu, s, 16);
                    s += __shfl_xor_sync(0xffffffffu, s, 8);
                    s += __shfl_xor_sync(0xffffffffu, s, 4);
                    s += __shfl_xor_sync(0xffffffffu, s, 2);
                    s += __shfl_xor_sync(0xffffffffu, s, 1);
                    if (lid == 0) part[sub][wid4] = s;
                }
                SUBBAR();
            }
        }
    }

    // ---- finish: alpha *= exp(trans[end]), norm = logc + log(sum) ----
    const int rbf = len & 1;
    float fv = abuf[sub][rbf][j] * __expf(trans[(LBLq - 1) * LBLq + j]);
    fv += __shfl_xor_sync(0xffffffffu, fv, 16);
    fv += __shfl_xor_sync(0xffffffffu, fv, 8);
    fv += __shfl_xor_sync(0xffffffffu, fv, 4);
    fv += __shfl_xor_sync(0xffffffffu, fv, 2);
    fv += __shfl_xor_sync(0xffffffffu, fv, 1);
    if (lid == 0) red[sub][wid4] = fv;
    SUBBAR();
    if (j == 0) {
        float fs = (red[sub][0] + red[sub][1]) + (red[sub][2] + red[sub][3]);
        out[b] = gold - (logc + __logf(fs));
    }
    #undef SUBBAR
}

extern "C" void kernel_launch(void* const* d_in, const int* in_sizes, int n_in,
                              void* d_out, int out_size) {
    const float* logits = (const float*)d_in[0];
    const int*   labels = (const int*)d_in[1];
    const int*   lens   = (const int*)d_in[2];
    const float* trans  = (const float*)d_in[3];
    float*       out    = (float*)d_out;

    rank_kernel<<<1, Bq>>>(lens);
    crf_kernel<<<Bq / 2, 256>>>(logits, labels, lens, trans, out);
}

// round 6
// speedup vs baseline: 1.2928x; 1.2818x over previous
#include <cuda_runtime.h>

#define Bq   256
#define Tq   1024
#define NUMq 126
#define LBLq 128
#define NSM  152

__device__ int d_perm[Bq];

// Rank sequences by length (desc) so each SM's CTA pair tends to be long+short.
__global__ void rank_kernel(const int* __restrict__ lens) {
    __shared__ int sl[Bq];
    int i = threadIdx.x;
    int li = lens[i];
    sl[i] = li;
    __syncthreads();
    int r = 0;
    #pragma unroll 8
    for (int k = 0; k < Bq; ++k) {
        int lk = sl[k];
        r += (lk > li) || (lk == li && k < i);
    }
    d_perm[r] = i;
}

__device__ __forceinline__ void fma2(unsigned long long& d,
                                     unsigned long long a, unsigned long long b) {
    asm("fma.rn.f32x2 %0, %1, %2, %0;" : "+l"(d) : "l"(a), "l"(b));
}
__device__ __forceinline__ unsigned long long add2(unsigned long long a,
                                                   unsigned long long b) {
    unsigned long long d;
    asm("add.rn.f32x2 %0, %1, %2;" : "=l"(d) : "l"(a), "l"(b));
    return d;
}
__device__ __forceinline__ unsigned long long pack2(float lo, float hi) {
    unsigned long long d;
    asm("mov.b64 %0, {%1, %2};" : "=l"(d) : "f"(lo), "f"(hi));
    return d;
}
__device__ __forceinline__ void unpack2(unsigned long long d, float& lo, float& hi) {
    asm("mov.b64 {%0, %1}, %2;" : "=f"(lo), "=f"(hi) : "l"(d));
}

__global__ __launch_bounds__(128, 2)
void crf_kernel(const float* __restrict__ logits,
                const int*   __restrict__ labels,
                const int*   __restrict__ lens,
                const float* __restrict__ trans,
                float*       __restrict__ out) {
    const int bid  = blockIdx.x;
    const int slot = (bid < NSM) ? bid : (Bq - 1 - (bid - NSM));
    const int b    = d_perm[slot];
    const int len  = lens[b];
    const int tid  = threadIdx.x;
    const int w    = tid >> 5;
    const int l    = tid & 31;
    const int c    = l >> 3;            // k-chunk (32 cols each)
    const int g    = l & 7;             // row-group within warp
    const int rowbase = w * 32 + g * 4; // this thread's 4 output rows

    __shared__ __align__(128) float abuf[2][LBLq];  // linear alpha, double buffered
    __shared__ float red[4];

    // ---- expT tile: 4 rows x 32 cols, stored in slot-rotated order so that
    // in load-slot s the four k-chunks hit distinct smem bank groups.
    unsigned long long R2[4][16];
    #pragma unroll
    for (int r = 0; r < 4; ++r) {
        const float* trow = trans + (rowbase + r) * LBLq + c * 32;
        #pragma unroll
        for (int s = 0; s < 8; ++s) {
            const float* src = trow + (((s + c) & 7) << 2);
            R2[r][2 * s]     = pack2(__expf(src[0]), __expf(src[1]));
            R2[r][2 * s + 1] = pack2(__expf(src[2]), __expf(src[3]));
        }
    }
    float vmask[4];
    #pragma unroll
    for (int r = 0; r < 4; ++r) vmask[r] = (rowbase + r < NUMq) ? 1.f : 0.f;

    // ---- gold path score (cooperative over t) ----
    const int lb = b * Tq;
    const float* lgb = logits + (size_t)lb * NUMq;
    float gacc = 0.f;
    for (int t = tid; t < len; t += 128) {
        int lab = labels[lb + t];
        gacc += lgb[t * NUMq + lab];
        int prev = (t == 0) ? (LBLq - 2) : labels[lb + t - 1];
        gacc += trans[lab * LBLq + prev];
    }
    if (tid == 0) gacc += trans[(LBLq - 1) * LBLq + labels[lb + len - 1]];
    gacc += __shfl_xor_sync(0xffffffffu, gacc, 16);
    gacc += __shfl_xor_sync(0xffffffffu, gacc, 8);
    gacc += __shfl_xor_sync(0xffffffffu, gacc, 4);
    gacc += __shfl_xor_sync(0xffffffffu, gacc, 2);
    gacc += __shfl_xor_sync(0xffffffffu, gacc, 1);
    if (l == 0) red[w] = gacc;
    __syncthreads();
    float gold = 0.f;
    if (tid == 0) gold = (red[0] + red[1]) + (red[2] + red[3]);

    // ---- init alpha0 = onehot(start=126) ----
    abuf[0][tid] = (tid == (LBLq - 2)) ? 1.0f : 0.0f;

    // ---- logit queues: cur = group 0, nxt = group 1, clamped addresses ----
    float cur[4][4], nxt[4][4];   // [phase][row]
    #pragma unroll
    for (int q = 0; q < 4; ++q)
        #pragma unroll
        for (int r = 0; r < 4; ++r) {
            int tt = (q < len) ? q : (len - 1);
            int rr = (rowbase + r < NUMq) ? (rowbase + r) : (NUMq - 1);
            cur[q][r] = lgb[tt * NUMq + rr];
            int t2 = (4 + q < len) ? (4 + q) : (len - 1);
            nxt[q][r] = lgb[t2 * NUMq + rr];
        }

    float logc = 0.f;
    float inv  = 1.0f;
    __syncthreads();

#define STEP(PH, T)                                                             \
    {                                                                           \
        const int rb = (PH) & 1, wb = 1 - rb;                                   \
        const ulonglong2* aa = (const ulonglong2*)(abuf[rb] + 32 * c);          \
        unsigned long long ax[4][2];                                            \
        _Pragma("unroll")                                                       \
        for (int r = 0; r < 4; ++r) { ax[r][0] = 0ull; ax[r][1] = 0ull; }       \
        unsigned long long sa0 = 0ull, sa1 = 0ull;                              \
        _Pragma("unroll")                                                       \
        for (int s = 0; s < 8; ++s) {                                           \
            ulonglong2 A = aa[(s + c) & 7];                                     \
            if ((PH) == 0) { sa0 = add2(sa0, A.x); sa1 = add2(sa1, A.y); }      \
            fma2(ax[0][0], R2[0][2 * s], A.x); fma2(ax[0][1], R2[0][2 * s + 1], A.y); \
            fma2(ax[1][0], R2[1][2 * s], A.x); fma2(ax[1][1], R2[1][2 * s + 1], A.y); \
            fma2(ax[2][0], R2[2][2 * s], A.x); fma2(ax[2][1], R2[2][2 * s + 1], A.y); \
            fma2(ax[3][0], R2[3][2 * s], A.x); fma2(ax[3][1], R2[3][2 * s + 1], A.y); \
        }                                                                       \
        if ((PH) == 0) {                                                        \
            float tlo, thi;                                                     \
            unpack2(add2(sa0, sa1), tlo, thi);                                  \
            float ts = tlo + thi;                                               \
            ts += __shfl_xor_sync(0xffffffffu, ts, 8);                          \
            ts += __shfl_xor_sync(0xffffffffu, ts, 16);                         \
            inv   = __fdividef(1.0f, ts);                                       \
            logc += __logf(ts);                                                 \
            if ((T) != 0) {                                                     \
                _Pragma("unroll")                                               \
                for (int q = 0; q < 4; ++q)                                     \
                    _Pragma("unroll")                                           \
                    for (int r = 0; r < 4; ++r) {                               \
                        cur[q][r] = nxt[q][r];                                  \
                        int tt = ((T) + 4 + q < len) ? ((T) + 4 + q) : (len - 1); \
                        int rr = (rowbase + r < NUMq) ? (rowbase + r) : (NUMq - 1); \
                        nxt[q][r] = lgb[tt * NUMq + rr];                        \
                    }                                                           \
            }                                                                   \
        }                                                                       \
        float vv0, vv1, vv2, vv3;                                               \
        {                                                                       \
            float lo, hi, ps;                                                   \
            unpack2(add2(ax[0][0], ax[0][1]), lo, hi); ps = lo + hi;            \
            ps += __shfl_xor_sync(0xffffffffu, ps, 8);                          \
            ps += __shfl_xor_sync(0xffffffffu, ps, 16);                         \
            float wg = __expf(cur[(PH)][0]) * vmask[0];                         \
            if ((PH) == 1) wg *= inv;                                           \
            vv0 = wg * ps;                                                      \
            unpack2(add2(ax[1][0], ax[1][1]), lo, hi); ps = lo + hi;            \
            ps += __shfl_xor_sync(0xffffffffu, ps, 8);                          \
            ps += __shfl_xor_sync(0xffffffffu, ps, 16);                         \
            wg = __expf(cur[(PH)][1]) * vmask[1];                               \
            if ((PH) == 1) wg *= inv;                                           \
            vv1 = wg * ps;                                                      \
            unpack2(add2(ax[2][0], ax[2][1]), lo, hi); ps = lo + hi;            \
            ps += __shfl_xor_sync(0xffffffffu, ps, 8);                          \
            ps += __shfl_xor_sync(0xffffffffu, ps, 16);                         \
            wg = __expf(cur[(PH)][2]) * vmask[2];                               \
            if ((PH) == 1) wg *= inv;                                           \
            vv2 = wg * ps;                                                      \
            unpack2(add2(ax[3][0], ax[3][1]), lo, hi); ps = lo + hi;            \
            ps += __shfl_xor_sync(0xffffffffu, ps, 8);                          \
            ps += __shfl_xor_sync(0xffffffffu, ps, 16);                         \
            wg = __expf(cur[(PH)][3]) * vmask[3];                               \
            if ((PH) == 1) wg *= inv;                                           \
            vv3 = wg * ps;                                                      \
        }                                                                       \
        if (c == 0)                                                             \
            *(float4*)&abuf[wb][rowbase] = make_float4(vv0, vv1, vv2, vv3);     \
        __syncthreads();                                                        \
    }

    int t0 = 0;
    for (; t0 + 4 <= len; t0 += 4) {
        STEP(0, t0)
        STEP(1, t0 + 1)
        STEP(2, t0 + 2)
        STEP(3, t0 + 3)
    }
    const int rem = len - t0;
    if (rem > 0) STEP(0, t0)
    if (rem > 1) STEP(1, t0 + 1)
    if (rem > 2) STEP(2, t0 + 2)
#undef STEP

    // ---- finish: alpha *= exp(trans[end]); fold pending inv if the sequence
    // ended right after a group head (inv computed but never applied).
    const int rbf = len & 1;
    float fv = abuf[rbf][tid] * __expf(trans[(LBLq - 1) * LBLq + tid]);
    if ((len & 3) == 1) fv *= inv;
    fv += __shfl_xor_sync(0xffffffffu, fv, 16);
    fv += __shfl_xor_sync(0xffffffffu, fv, 8);
    fv += __shfl_xor_sync(0xffffffffu, fv, 4);
    fv += __shfl_xor_sync(0xffffffffu, fv, 2);
    fv += __shfl_xor_sync(0xffffffffu, fv, 1);
    if (l == 0) red[w] = fv;
    __syncthreads();
    if (tid == 0) {
        float fs = (red[0] + red[1]) + (red[2] + red[3]);
        out[b] = gold - (logc + __logf(fs));
    }
}

extern "C" void kernel_launch(void* const* d_in, const int* in_sizes, int n_in,
                              void* d_out, int out_size) {
    const float* logits = (const float*)d_in[0];
    const int*   labels = (const int*)d_in[1];
    const int*   lens   = (const int*)d_in[2];
    const float* trans  = (const float*)d_in[3];
    float*       out    = (float*)d_out;

    rank_kernel<<<1, Bq>>>(lens);
    crf_kernel<<<Bq, 128>>>(logits, labels, lens, trans, out);
}